// round 3
// baseline (speedup 1.0000x reference)
#include <cuda_runtime.h>
#include <cuda_bf16.h>

// Problem constants
#define NN 50000
#define EE 500000
#define F_IN 64
#define E_IN 16
#define HH 100
#define NL 2

// Scratch (device globals; no dynamic allocation allowed)
// node-sized buffers: h, agg(z), t1, P, Q  (each 5e6 floats = 20MB)
__device__ float g_buf_node[6u * 5000000u];
// edge-sized buffers: e, tbuf  (each 5e7 floats = 200MB)
__device__ float g_buf_edge[2u * 50000000u];
__device__ float g_stats[256];

// ---------------------------------------------------------------------------
// fp32 tiled GEMM with fused epilogues.
// C[M,N] = A[M,K] @ B[K,N], block tile 128x128, K-chunk 16, 256 thr, 8x8/thr.
// mode 0: C = acc + bias(optional)
// mode 1: C = relu(acc + bias)
// mode 2: C = relu(acc + P[src[r]] + Q[dst[r]] + bias)   (gather epilogue)
// mode 3: C += 0.5f * (acc + bias)                        (residual update)
// ---------------------------------------------------------------------------
__global__ __launch_bounds__(256) void sgemm_kernel(
    const float* __restrict__ A, const float* __restrict__ B,
    float* __restrict__ C, const float* __restrict__ bias,
    int M, int N, int K, int lda, int ldb, int ldc, int mode,
    const int* __restrict__ src, const int* __restrict__ dst,
    const float* __restrict__ P, const float* __restrict__ Q, int ldpq)
{
    __shared__ float As[16][128];
    __shared__ float Bs[16][128];

    const int t = threadIdx.x;
    const int tx = t & 15;        // N-dir thread coord
    const int ty = t >> 4;        // M-dir thread coord
    const int row0 = blockIdx.y * 128;
    const int col0 = blockIdx.x * 128;

    const int a_m = t >> 1;          // 0..127
    const int a_k = (t & 1) * 8;     // 0 or 8
    const int b_k = t >> 4;          // 0..15
    const int b_n = (t & 15) * 8;    // 0..120

    float acc[8][8];
#pragma unroll
    for (int i = 0; i < 8; i++)
#pragma unroll
        for (int j = 0; j < 8; j++) acc[i][j] = 0.f;

    for (int k0 = 0; k0 < K; k0 += 16) {
        const int arow = row0 + a_m;
#pragma unroll
        for (int i = 0; i < 8; i++) {
            int k = k0 + a_k + i;
            float v = 0.f;
            if (arow < M && k < K) v = A[(size_t)arow * lda + k];
            As[a_k + i][a_m] = v;
        }
        {
            int k = k0 + b_k;
#pragma unroll
            for (int i = 0; i < 8; i++) {
                int n = col0 + b_n + i;
                float v = 0.f;
                if (k < K && n < N) v = B[(size_t)k * ldb + n];
                Bs[b_k][b_n + i] = v;
            }
        }
        __syncthreads();
#pragma unroll
        for (int kk = 0; kk < 16; kk++) {
            float a[8], b[8];
#pragma unroll
            for (int i = 0; i < 8; i++) a[i] = As[kk][ty * 8 + i];
#pragma unroll
            for (int j = 0; j < 8; j++) b[j] = Bs[kk][tx * 8 + j];
#pragma unroll
            for (int i = 0; i < 8; i++)
#pragma unroll
                for (int j = 0; j < 8; j++)
                    acc[i][j] = fmaf(a[i], b[j], acc[i][j]);
        }
        __syncthreads();
    }

    float bv[8];
#pragma unroll
    for (int j = 0; j < 8; j++) {
        int c = col0 + tx * 8 + j;
        bv[j] = (bias && c < N) ? bias[c] : 0.f;
    }

#pragma unroll
    for (int i = 0; i < 8; i++) {
        int r = row0 + ty * 8 + i;
        if (r >= M) continue;
        float* crow = C + (size_t)r * ldc;
        if (mode == 2) {
            int s = src[r], d = dst[r];
            const float* prow = P + (size_t)s * ldpq;
            const float* qrow = Q + (size_t)d * ldpq;
#pragma unroll
            for (int j = 0; j < 8; j++) {
                int c = col0 + tx * 8 + j;
                if (c >= N) continue;
                float v = acc[i][j] + bv[j] + prow[c] + qrow[c];
                crow[c] = fmaxf(v, 0.f);
            }
        } else if (mode == 3) {
#pragma unroll
            for (int j = 0; j < 8; j++) {
                int c = col0 + tx * 8 + j;
                if (c >= N) continue;
                crow[c] += 0.5f * (acc[i][j] + bv[j]);
            }
        } else {
#pragma unroll
            for (int j = 0; j < 8; j++) {
                int c = col0 + tx * 8 + j;
                if (c >= N) continue;
                float v = acc[i][j] + bv[j];
                if (mode == 1) v = fmaxf(v, 0.f);
                crow[c] = v;
            }
        }
    }
}

// ---------------------------------------------------------------------------
// Elementwise / graph kernels
// ---------------------------------------------------------------------------
__global__ void copy_kernel(float* __restrict__ dst_, const float* __restrict__ src_, int n)
{
    int i = blockIdx.x * blockDim.x + threadIdx.x;
    if (i < n) dst_[i] = src_[i];
}

// msg = relu(h[src] + e); agg[dst] += msg   (thread per (edge, float4-chunk))
// sm_90+: HW vector atomicAdd on float4 (rows are 400B, chunks 16B aligned).
__global__ void scatter_kernel(const float* __restrict__ h, const float* __restrict__ e,
                               const int* __restrict__ src, const int* __restrict__ dst,
                               float* __restrict__ agg)
{
    int idx = blockIdx.x * blockDim.x + threadIdx.x;
    if (idx >= EE * 25) return;
    int edge = idx / 25, j = idx % 25;
    int s = src[edge], d = dst[edge];
    float4 ev = reinterpret_cast<const float4*>(e)[edge * 25 + j];
    float4 hv = reinterpret_cast<const float4*>(h)[(size_t)s * 25 + j];
    float4 m;
    m.x = fmaxf(ev.x + hv.x, 0.f);
    m.y = fmaxf(ev.y + hv.y, 0.f);
    m.z = fmaxf(ev.z + hv.z, 0.f);
    m.w = fmaxf(ev.w + hv.w, 0.f);
    float4* ap = reinterpret_cast<float4*>(agg + (size_t)d * HH) + j;
    atomicAdd(ap, m);
}

// per-column mean and rstd over NN rows (one block per column)
__global__ void bn_stats_kernel(const float* __restrict__ z, float* __restrict__ mean,
                                float* __restrict__ rstd)
{
    __shared__ float sh[256], sh2[256];
    int c = blockIdx.x;
    float s = 0.f, s2 = 0.f;
    for (int r = threadIdx.x; r < NN; r += 256) {
        float v = z[(size_t)r * HH + c];
        s += v; s2 += v * v;
    }
    sh[threadIdx.x] = s; sh2[threadIdx.x] = s2;
    __syncthreads();
    for (int o = 128; o > 0; o >>= 1) {
        if (threadIdx.x < o) {
            sh[threadIdx.x] += sh[threadIdx.x + o];
            sh2[threadIdx.x] += sh2[threadIdx.x + o];
        }
        __syncthreads();
    }
    if (threadIdx.x == 0) {
        float mu = sh[0] / (float)NN;
        float var = sh2[0] / (float)NN - mu * mu;
        mean[c] = mu;
        rstd[c] = rsqrtf(fmaxf(var, 0.f) + 1e-5f);
    }
}

// h = (h + relu(bn(z))) * 0.5
__global__ void h_update_kernel(float* __restrict__ h, const float* __restrict__ z,
                                const float* __restrict__ mean, const float* __restrict__ rstd,
                                const float* __restrict__ gamma, const float* __restrict__ beta,
                                int n)
{
    int i = blockIdx.x * blockDim.x + threadIdx.x;
    if (i >= n) return;
    int c = i % HH;
    float zn = (z[i] - mean[c]) * rstd[c] * gamma[c] + beta[c];
    h[i] = (h[i] + fmaxf(zn, 0.f)) * 0.5f;
}

__global__ void relu_copy_kernel(float* __restrict__ dst_, const float* __restrict__ src_, int n)
{
    int i = blockIdx.x * blockDim.x + threadIdx.x;
    if (i < n) dst_[i] = fmaxf(src_[i], 0.f);
}

// out[E,2] = o2[E,25] @ w3[25,2] + b3
__global__ void out_kernel(const float* __restrict__ o2, const float* __restrict__ w3,
                           const float* __restrict__ b3, float* __restrict__ out)
{
    __shared__ float w[50];
    __shared__ float b[2];
    if (threadIdx.x < 50) w[threadIdx.x] = w3[threadIdx.x];
    if (threadIdx.x < 2) b[threadIdx.x] = b3[threadIdx.x];
    __syncthreads();
    int eIdx = blockIdx.x * blockDim.x + threadIdx.x;
    if (eIdx >= EE) return;
    float a0 = b[0], a1 = b[1];
    const float* row = o2 + (size_t)eIdx * 25;
#pragma unroll
    for (int k = 0; k < 25; k++) {
        float v = row[k];
        a0 = fmaf(v, w[2 * k], a0);
        a1 = fmaf(v, w[2 * k + 1], a1);
    }
    out[eIdx * 2] = a0;
    out[eIdx * 2 + 1] = a1;
}

// ---------------------------------------------------------------------------
// Host launcher
// ---------------------------------------------------------------------------
static inline void launch_gemm(const float* A, const float* B, float* C, const float* bias,
                               int M, int N, int K, int lda, int ldb, int ldc, int mode,
                               const int* src = nullptr, const int* dst = nullptr,
                               const float* P = nullptr, const float* Q = nullptr, int ldpq = 0)
{
    dim3 grid((N + 127) / 128, (M + 127) / 128);
    sgemm_kernel<<<grid, 256>>>(A, B, C, bias, M, N, K, lda, ldb, ldc, mode,
                                src, dst, P, Q, ldpq);
}

extern "C" void kernel_launch(void* const* d_in, const int* in_sizes, int n_in,
                              void* d_out, int out_size)
{
    const float* x       = (const float*)d_in[0];
    const float* ea      = (const float*)d_in[1];
    const int*   ei      = (const int*)d_in[2];
    const float* node_w  = (const float*)d_in[3];
    const float* node_b  = (const float*)d_in[4];
    const float* edge_w  = (const float*)d_in[5];
    const float* edge_b  = (const float*)d_in[6];
    const float* gine_w1 = (const float*)d_in[7];
    const float* gine_b1 = (const float*)d_in[8];
    const float* gine_w2 = (const float*)d_in[9];
    const float* gine_b2 = (const float*)d_in[10];
    const float* bn_g    = (const float*)d_in[11];
    const float* bn_b    = (const float*)d_in[12];
    const float* emlp_w1 = (const float*)d_in[13];
    const float* emlp_b1 = (const float*)d_in[14];
    const float* emlp_w2 = (const float*)d_in[15];
    const float* emlp_b2 = (const float*)d_in[16];
    const float* mlp_w1  = (const float*)d_in[17];
    const float* mlp_b1  = (const float*)d_in[18];
    const float* mlp_w2  = (const float*)d_in[19];
    const float* mlp_b2  = (const float*)d_in[20];
    const float* mlp_w3  = (const float*)d_in[21];
    const float* mlp_b3  = (const float*)d_in[22];

    void* pv;
    cudaGetSymbolAddress(&pv, g_buf_node);
    float* nb = (float*)pv;
    float* h   = nb;                       // [N,H]
    float* agg = nb + 1u * 5000000u;       // [N,H]  (doubles as z)
    float* t1  = nb + 2u * 5000000u;       // [N,H]
    float* P   = nb + 3u * 5000000u;       // [N,H]
    float* Q   = nb + 4u * 5000000u;       // [N,H]
    float* z2  = nb + 5u * 5000000u;       // [N,H]  (gine MLP output)
    cudaGetSymbolAddress(&pv, g_buf_edge);
    float* eb = (float*)pv;
    float* e    = eb;
    float* tbuf = eb + 1u * 50000000u;
    cudaGetSymbolAddress(&pv, g_stats);
    float* mean = (float*)pv;
    float* rstd = mean + 128;

    const int* src = ei;
    const int* dst = ei + EE;

    const int NH = NN * HH;          // 5,000,000
    const int ECH = EE * 25;         // 12,500,000 (float4 chunks over E*100)
    dim3 blk(256);
    int gNH = (NH + 255) / 256;
    int gECH = (ECH + 255) / 256;

    // embeddings
    launch_gemm(x, node_w, h, node_b, NN, HH, F_IN, F_IN, HH, HH, 0);
    launch_gemm(ea, edge_w, e, edge_b, EE, HH, E_IN, E_IN, HH, HH, 0);

    for (int i = 0; i < NL; i++) {
        const float* gw1 = gine_w1 + i * HH * HH;
        const float* gb1 = gine_b1 + i * HH;
        const float* gw2 = gine_w2 + i * HH * HH;
        const float* gb2 = gine_b2 + i * HH;
        const float* ew1 = emlp_w1 + i * 3 * HH * HH;   // [300,100]
        const float* eb1 = emlp_b1 + i * HH;
        const float* ew2 = emlp_w2 + i * HH * HH;
        const float* eb2 = emlp_b2 + i * HH;

        // aggregate messages: agg = h (init) then agg[dst] += relu(h[src]+e)
        // -> agg ends up equal to z = h + segment_sum(msg)
        copy_kernel<<<gNH, blk>>>(agg, h, NH);
        scatter_kernel<<<gECH, blk>>>(h, e, src, dst, agg);

        // GINE node MLP: z2 = relu(agg@gw1+gb1)@gw2+gb2
        launch_gemm(agg, gw1, t1, gb1, NN, HH, HH, HH, HH, HH, 1);
        launch_gemm(t1, gw2, z2, gb2, NN, HH, HH, HH, HH, HH, 0);

        // batchnorm + residual update of h
        bn_stats_kernel<<<HH, blk>>>(z2, mean, rstd);
        h_update_kernel<<<gNH, blk>>>(h, z2, mean, rstd, bn_g + i * HH, bn_b + i * HH, NH);

        // edge MLP, factored: cat@W1 = h@W1[0:100] + h@W1[100:200] + e@W1[200:300]
        launch_gemm(h, ew1,            P, nullptr, NN, HH, HH, HH, HH, HH, 0);
        launch_gemm(h, ew1 + 100 * HH, Q, nullptr, NN, HH, HH, HH, HH, HH, 0);
        // tbuf = relu(e@W1c + P[src] + Q[dst] + b1)   (fused gather epilogue)
        launch_gemm(e, ew1 + 200 * HH, tbuf, eb1, EE, HH, HH, HH, HH, HH, 2,
                    src, dst, P, Q, HH);
        // e += 0.5 * (tbuf@W2 + b2)                    (fused residual epilogue)
        launch_gemm(tbuf, ew2, e, eb2, EE, HH, HH, HH, HH, HH, 3);
    }

    // readout, factored the same way (relu(cat(h_s,h_d)) = cat(relu(h_s),relu(h_d)))
    relu_copy_kernel<<<gNH, blk>>>(t1, h, NH);
    launch_gemm(t1, mlp_w1,            P, nullptr, NN, 50, HH, HH, 50, 50, 0);
    launch_gemm(t1, mlp_w1 + 100 * 50, Q, nullptr, NN, 50, HH, HH, 50, 50, 0);
    // o1 = relu(e@W1c + P[src] + Q[dst] + b1)  [E,50]  (fused gather epilogue)
    launch_gemm(e, mlp_w1 + 200 * 50, tbuf, mlp_b1, EE, 50, HH, HH, 50, 50, 2,
                src, dst, P, Q, 50);
    // o2 = relu(o1@W2 + b2)  [E,25]
    launch_gemm(tbuf, mlp_w2, tbuf + 25000000u, mlp_b2, EE, 25, 50, 50, 25, 25, 1);
    out_kernel<<<(EE + 255) / 256, blk>>>(tbuf + 25000000u, mlp_w3, mlp_b3, (float*)d_out);
}

// round 4
// speedup vs baseline: 1.0004x; 1.0004x over previous
#include <cuda_runtime.h>
#include <cuda_bf16.h>

// Problem constants
#define NN 50000
#define EE 500000
#define F_IN 64
#define E_IN 16
#define HH 100
#define NL 2

// Scratch (device globals; no dynamic allocation allowed)
// node-sized buffers: h, agg(z), t1, P, Q  (each 5e6 floats = 20MB)
__device__ float g_buf_node[6u * 5000000u];
// edge-sized buffers: e, tbuf  (each 5e7 floats = 200MB)
__device__ float g_buf_edge[2u * 50000000u];
__device__ float g_stats[256];

// ---------------------------------------------------------------------------
// fp32 tiled GEMM with fused epilogues.
// C[M,N] = A[M,K] @ B[K,N], block tile 128x128, K-chunk 16, 256 thr, 8x8/thr.
// mode 0: C = acc + bias(optional)
// mode 1: C = relu(acc + bias)
// mode 2: C = relu(acc + P[src[r]] + Q[dst[r]] + bias)   (gather epilogue)
// mode 3: C += 0.5f * (acc + bias)                        (residual update)
// ---------------------------------------------------------------------------
__global__ __launch_bounds__(256) void sgemm_kernel(
    const float* __restrict__ A, const float* __restrict__ B,
    float* __restrict__ C, const float* __restrict__ bias,
    int M, int N, int K, int lda, int ldb, int ldc, int mode,
    const int* __restrict__ src, const int* __restrict__ dst,
    const float* __restrict__ P, const float* __restrict__ Q, int ldpq)
{
    __shared__ float As[16][128];
    __shared__ float Bs[16][128];

    const int t = threadIdx.x;
    const int tx = t & 15;        // N-dir thread coord
    const int ty = t >> 4;        // M-dir thread coord
    const int row0 = blockIdx.y * 128;
    const int col0 = blockIdx.x * 128;

    const int a_m = t >> 1;          // 0..127
    const int a_k = (t & 1) * 8;     // 0 or 8
    const int b_k = t >> 4;          // 0..15
    const int b_n = (t & 15) * 8;    // 0..120

    float acc[8][8];
#pragma unroll
    for (int i = 0; i < 8; i++)
#pragma unroll
        for (int j = 0; j < 8; j++) acc[i][j] = 0.f;

    for (int k0 = 0; k0 < K; k0 += 16) {
        const int arow = row0 + a_m;
#pragma unroll
        for (int i = 0; i < 8; i++) {
            int k = k0 + a_k + i;
            float v = 0.f;
            if (arow < M && k < K) v = A[(size_t)arow * lda + k];
            As[a_k + i][a_m] = v;
        }
        {
            int k = k0 + b_k;
#pragma unroll
            for (int i = 0; i < 8; i++) {
                int n = col0 + b_n + i;
                float v = 0.f;
                if (k < K && n < N) v = B[(size_t)k * ldb + n];
                Bs[b_k][b_n + i] = v;
            }
        }
        __syncthreads();
#pragma unroll
        for (int kk = 0; kk < 16; kk++) {
            float a[8], b[8];
#pragma unroll
            for (int i = 0; i < 8; i++) a[i] = As[kk][ty * 8 + i];
#pragma unroll
            for (int j = 0; j < 8; j++) b[j] = Bs[kk][tx * 8 + j];
#pragma unroll
            for (int i = 0; i < 8; i++)
#pragma unroll
                for (int j = 0; j < 8; j++)
                    acc[i][j] = fmaf(a[i], b[j], acc[i][j]);
        }
        __syncthreads();
    }

    float bv[8];
#pragma unroll
    for (int j = 0; j < 8; j++) {
        int c = col0 + tx * 8 + j;
        bv[j] = (bias && c < N) ? bias[c] : 0.f;
    }

#pragma unroll
    for (int i = 0; i < 8; i++) {
        int r = row0 + ty * 8 + i;
        if (r >= M) continue;
        float* crow = C + (size_t)r * ldc;
        if (mode == 2) {
            int s = src[r], d = dst[r];
            const float* prow = P + (size_t)s * ldpq;
            const float* qrow = Q + (size_t)d * ldpq;
#pragma unroll
            for (int j = 0; j < 8; j++) {
                int c = col0 + tx * 8 + j;
                if (c >= N) continue;
                float v = acc[i][j] + bv[j] + prow[c] + qrow[c];
                crow[c] = fmaxf(v, 0.f);
            }
        } else if (mode == 3) {
#pragma unroll
            for (int j = 0; j < 8; j++) {
                int c = col0 + tx * 8 + j;
                if (c >= N) continue;
                crow[c] += 0.5f * (acc[i][j] + bv[j]);
            }
        } else {
#pragma unroll
            for (int j = 0; j < 8; j++) {
                int c = col0 + tx * 8 + j;
                if (c >= N) continue;
                float v = acc[i][j] + bv[j];
                if (mode == 1) v = fmaxf(v, 0.f);
                crow[c] = v;
            }
        }
    }
}

// ---------------------------------------------------------------------------
// Elementwise / graph kernels
// ---------------------------------------------------------------------------
__global__ void copy_kernel(float* __restrict__ dst_, const float* __restrict__ src_, int n)
{
    int i = blockIdx.x * blockDim.x + threadIdx.x;
    if (i < n) dst_[i] = src_[i];
}

// msg = relu(h[src] + e); agg[dst] += msg   (thread per (edge, float4-chunk))
// sm_90+: HW vector atomicAdd on float4 (rows are 400B, chunks 16B aligned).
__global__ void scatter_kernel(const float* __restrict__ h, const float* __restrict__ e,
                               const int* __restrict__ src, const int* __restrict__ dst,
                               float* __restrict__ agg)
{
    int idx = blockIdx.x * blockDim.x + threadIdx.x;
    if (idx >= EE * 25) return;
    int edge = idx / 25, j = idx % 25;
    int s = src[edge], d = dst[edge];
    float4 ev = reinterpret_cast<const float4*>(e)[edge * 25 + j];
    float4 hv = reinterpret_cast<const float4*>(h)[(size_t)s * 25 + j];
    float4 m;
    m.x = fmaxf(ev.x + hv.x, 0.f);
    m.y = fmaxf(ev.y + hv.y, 0.f);
    m.z = fmaxf(ev.z + hv.z, 0.f);
    m.w = fmaxf(ev.w + hv.w, 0.f);
    float4* ap = reinterpret_cast<float4*>(agg + (size_t)d * HH) + j;
    atomicAdd(ap, m);
}

// per-column mean and rstd over NN rows (one block per column)
__global__ void bn_stats_kernel(const float* __restrict__ z, float* __restrict__ mean,
                                float* __restrict__ rstd)
{
    __shared__ float sh[256], sh2[256];
    int c = blockIdx.x;
    float s = 0.f, s2 = 0.f;
    for (int r = threadIdx.x; r < NN; r += 256) {
        float v = z[(size_t)r * HH + c];
        s += v; s2 += v * v;
    }
    sh[threadIdx.x] = s; sh2[threadIdx.x] = s2;
    __syncthreads();
    for (int o = 128; o > 0; o >>= 1) {
        if (threadIdx.x < o) {
            sh[threadIdx.x] += sh[threadIdx.x + o];
            sh2[threadIdx.x] += sh2[threadIdx.x + o];
        }
        __syncthreads();
    }
    if (threadIdx.x == 0) {
        float mu = sh[0] / (float)NN;
        float var = sh2[0] / (float)NN - mu * mu;
        mean[c] = mu;
        rstd[c] = rsqrtf(fmaxf(var, 0.f) + 1e-5f);
    }
}

// h = (h + relu(bn(z))) * 0.5
__global__ void h_update_kernel(float* __restrict__ h, const float* __restrict__ z,
                                const float* __restrict__ mean, const float* __restrict__ rstd,
                                const float* __restrict__ gamma, const float* __restrict__ beta,
                                int n)
{
    int i = blockIdx.x * blockDim.x + threadIdx.x;
    if (i >= n) return;
    int c = i % HH;
    float zn = (z[i] - mean[c]) * rstd[c] * gamma[c] + beta[c];
    h[i] = (h[i] + fmaxf(zn, 0.f)) * 0.5f;
}

__global__ void relu_copy_kernel(float* __restrict__ dst_, const float* __restrict__ src_, int n)
{
    int i = blockIdx.x * blockDim.x + threadIdx.x;
    if (i < n) dst_[i] = fmaxf(src_[i], 0.f);
}

// out[E,2] = o2[E,25] @ w3[25,2] + b3
__global__ void out_kernel(const float* __restrict__ o2, const float* __restrict__ w3,
                           const float* __restrict__ b3, float* __restrict__ out)
{
    __shared__ float w[50];
    __shared__ float b[2];
    if (threadIdx.x < 50) w[threadIdx.x] = w3[threadIdx.x];
    if (threadIdx.x < 2) b[threadIdx.x] = b3[threadIdx.x];
    __syncthreads();
    int eIdx = blockIdx.x * blockDim.x + threadIdx.x;
    if (eIdx >= EE) return;
    float a0 = b[0], a1 = b[1];
    const float* row = o2 + (size_t)eIdx * 25;
#pragma unroll
    for (int k = 0; k < 25; k++) {
        float v = row[k];
        a0 = fmaf(v, w[2 * k], a0);
        a1 = fmaf(v, w[2 * k + 1], a1);
    }
    out[eIdx * 2] = a0;
    out[eIdx * 2 + 1] = a1;
}

// ---------------------------------------------------------------------------
// Host launcher
// ---------------------------------------------------------------------------
static inline void launch_gemm(const float* A, const float* B, float* C, const float* bias,
                               int M, int N, int K, int lda, int ldb, int ldc, int mode,
                               const int* src = nullptr, const int* dst = nullptr,
                               const float* P = nullptr, const float* Q = nullptr, int ldpq = 0)
{
    dim3 grid((N + 127) / 128, (M + 127) / 128);
    sgemm_kernel<<<grid, 256>>>(A, B, C, bias, M, N, K, lda, ldb, ldc, mode,
                                src, dst, P, Q, ldpq);
}

extern "C" void kernel_launch(void* const* d_in, const int* in_sizes, int n_in,
                              void* d_out, int out_size)
{
    const float* x       = (const float*)d_in[0];
    const float* ea      = (const float*)d_in[1];
    const int*   ei      = (const int*)d_in[2];
    const float* node_w  = (const float*)d_in[3];
    const float* node_b  = (const float*)d_in[4];
    const float* edge_w  = (const float*)d_in[5];
    const float* edge_b  = (const float*)d_in[6];
    const float* gine_w1 = (const float*)d_in[7];
    const float* gine_b1 = (const float*)d_in[8];
    const float* gine_w2 = (const float*)d_in[9];
    const float* gine_b2 = (const float*)d_in[10];
    const float* bn_g    = (const float*)d_in[11];
    const float* bn_b    = (const float*)d_in[12];
    const float* emlp_w1 = (const float*)d_in[13];
    const float* emlp_b1 = (const float*)d_in[14];
    const float* emlp_w2 = (const float*)d_in[15];
    const float* emlp_b2 = (const float*)d_in[16];
    const float* mlp_w1  = (const float*)d_in[17];
    const float* mlp_b1  = (const float*)d_in[18];
    const float* mlp_w2  = (const float*)d_in[19];
    const float* mlp_b2  = (const float*)d_in[20];
    const float* mlp_w3  = (const float*)d_in[21];
    const float* mlp_b3  = (const float*)d_in[22];

    void* pv;
    cudaGetSymbolAddress(&pv, g_buf_node);
    float* nb = (float*)pv;
    float* h   = nb;                       // [N,H]
    float* agg = nb + 1u * 5000000u;       // [N,H]  (doubles as z)
    float* t1  = nb + 2u * 5000000u;       // [N,H]
    float* P   = nb + 3u * 5000000u;       // [N,H]
    float* Q   = nb + 4u * 5000000u;       // [N,H]
    float* z2  = nb + 5u * 5000000u;       // [N,H]  (gine MLP output)
    cudaGetSymbolAddress(&pv, g_buf_edge);
    float* eb = (float*)pv;
    float* e    = eb;
    float* tbuf = eb + 1u * 50000000u;
    cudaGetSymbolAddress(&pv, g_stats);
    float* mean = (float*)pv;
    float* rstd = mean + 128;

    const int* src = ei;
    const int* dst = ei + EE;

    const int NH = NN * HH;          // 5,000,000
    const int ECH = EE * 25;         // 12,500,000 (float4 chunks over E*100)
    dim3 blk(256);
    int gNH = (NH + 255) / 256;
    int gECH = (ECH + 255) / 256;

    // embeddings
    launch_gemm(x, node_w, h, node_b, NN, HH, F_IN, F_IN, HH, HH, 0);
    launch_gemm(ea, edge_w, e, edge_b, EE, HH, E_IN, E_IN, HH, HH, 0);

    for (int i = 0; i < NL; i++) {
        const float* gw1 = gine_w1 + i * HH * HH;
        const float* gb1 = gine_b1 + i * HH;
        const float* gw2 = gine_w2 + i * HH * HH;
        const float* gb2 = gine_b2 + i * HH;
        const float* ew1 = emlp_w1 + i * 3 * HH * HH;   // [300,100]
        const float* eb1 = emlp_b1 + i * HH;
        const float* ew2 = emlp_w2 + i * HH * HH;
        const float* eb2 = emlp_b2 + i * HH;

        // aggregate messages: agg = h (init) then agg[dst] += relu(h[src]+e)
        // -> agg ends up equal to z = h + segment_sum(msg)
        copy_kernel<<<gNH, blk>>>(agg, h, NH);
        scatter_kernel<<<gECH, blk>>>(h, e, src, dst, agg);

        // GINE node MLP: z2 = relu(agg@gw1+gb1)@gw2+gb2
        launch_gemm(agg, gw1, t1, gb1, NN, HH, HH, HH, HH, HH, 1);
        launch_gemm(t1, gw2, z2, gb2, NN, HH, HH, HH, HH, HH, 0);

        // batchnorm + residual update of h
        bn_stats_kernel<<<HH, blk>>>(z2, mean, rstd);
        h_update_kernel<<<gNH, blk>>>(h, z2, mean, rstd, bn_g + i * HH, bn_b + i * HH, NH);

        // edge MLP, factored: cat@W1 = h@W1[0:100] + h@W1[100:200] + e@W1[200:300]
        launch_gemm(h, ew1,            P, nullptr, NN, HH, HH, HH, HH, HH, 0);
        launch_gemm(h, ew1 + 100 * HH, Q, nullptr, NN, HH, HH, HH, HH, HH, 0);
        // tbuf = relu(e@W1c + P[src] + Q[dst] + b1)   (fused gather epilogue)
        launch_gemm(e, ew1 + 200 * HH, tbuf, eb1, EE, HH, HH, HH, HH, HH, 2,
                    src, dst, P, Q, HH);
        // e += 0.5 * (tbuf@W2 + b2)                    (fused residual epilogue)
        launch_gemm(tbuf, ew2, e, eb2, EE, HH, HH, HH, HH, HH, 3);
    }

    // readout, factored the same way (relu(cat(h_s,h_d)) = cat(relu(h_s),relu(h_d)))
    relu_copy_kernel<<<gNH, blk>>>(t1, h, NH);
    launch_gemm(t1, mlp_w1,            P, nullptr, NN, 50, HH, HH, 50, 50, 0);
    launch_gemm(t1, mlp_w1 + 100 * 50, Q, nullptr, NN, 50, HH, HH, 50, 50, 0);
    // o1 = relu(e@W1c + P[src] + Q[dst] + b1)  [E,50]  (fused gather epilogue)
    launch_gemm(e, mlp_w1 + 200 * 50, tbuf, mlp_b1, EE, 50, HH, HH, 50, 50, 2,
                src, dst, P, Q, 50);
    // o2 = relu(o1@W2 + b2)  [E,25]
    launch_gemm(tbuf, mlp_w2, tbuf + 25000000u, mlp_b2, EE, 25, 50, 50, 25, 25, 1);
    out_kernel<<<(EE + 255) / 256, blk>>>(tbuf + 25000000u, mlp_w3, mlp_b3, (float*)d_out);
}